// round 12
// baseline (speedup 1.0000x reference)
#include <cuda_runtime.h>
#include <cuda_bf16.h>
#include <stdint.h>

#define DI __device__ __forceinline__

// Scratch (device globals: allocation-free contract)
__device__ __nv_bfloat16 g_kb[4096 * 1024];   // keys bf16
__device__ __nv_bfloat16 g_vb[4096 * 1024];   // values bf16
__device__ __nv_bfloat16 g_wkb[512 * 1024];   // Wk_f bf16
__device__ __nv_bfloat16 g_wvb[512 * 1024];   // Wv_f bf16
__device__ __align__(16) float g_wot[1024 * 512];  // Wo[:, :512] tf32-rounded
__device__ __nv_bfloat16 g_fk[4096 * 512];    // gated K halves [B*NK, 512]
__device__ __nv_bfloat16 g_fvT[512 * 4096];   // gated V halves, transposed
__device__ __align__(16) float g_ao[4096 * 512];   // attention out (tf32-rounded)
__device__ float         g_cvec[1024];        // bo + v_sum @ Wo[:,512:].T
__device__ __align__(16) uint32_t g_mbits[16 * 2048 * 64];  // mask bitset, heads 0..7
__device__ int           g_mask_u8;

DI uint32_t pack_bf16(float a, float b) {
    __nv_bfloat162 t = __floats2bfloat162_rn(a, b);
    return *reinterpret_cast<uint32_t*>(&t);
}
DI uint32_t f2tf32(float f) {
    uint32_t r;
    asm("cvt.rna.tf32.f32 %0, %1;" : "=r"(r) : "f"(f));
    return r;
}
DI float ex2(float x) {
    float r;
    asm("ex2.approx.f32 %0, %1;" : "=f"(r) : "f"(x));
    return r;
}
DI void mma_bf16(float* c, uint32_t a0, uint32_t a1, uint32_t a2, uint32_t a3,
                 uint32_t b0, uint32_t b1) {
    asm volatile(
        "mma.sync.aligned.m16n8k16.row.col.f32.bf16.bf16.f32 "
        "{%0,%1,%2,%3}, {%4,%5,%6,%7}, {%8,%9}, {%0,%1,%2,%3};\n"
        : "+f"(c[0]), "+f"(c[1]), "+f"(c[2]), "+f"(c[3])
        : "r"(a0), "r"(a1), "r"(a2), "r"(a3), "r"(b0), "r"(b1));
}
DI void mma_tf32(float* c, uint32_t a0, uint32_t a1, uint32_t a2, uint32_t a3,
                 uint32_t b0, uint32_t b1) {
    asm volatile(
        "mma.sync.aligned.m16n8k8.row.col.f32.tf32.tf32.f32 "
        "{%0,%1,%2,%3}, {%4,%5,%6,%7}, {%8,%9}, {%0,%1,%2,%3};\n"
        : "+f"(c[0]), "+f"(c[1]), "+f"(c[2]), "+f"(c[3])
        : "r"(a0), "r"(a1), "r"(a2), "r"(a3), "r"(b0), "r"(b1));
}
DI void ldsm4(uint32_t& r0, uint32_t& r1, uint32_t& r2, uint32_t& r3, uint32_t saddr) {
    asm volatile("ldmatrix.sync.aligned.m8n8.x4.shared.b16 {%0,%1,%2,%3}, [%4];"
                 : "=r"(r0), "=r"(r1), "=r"(r2), "=r"(r3) : "r"(saddr));
}
DI void cp_async16(void* smem, const void* gmem) {
    uint32_t s = (uint32_t)__cvta_generic_to_shared(smem);
    asm volatile("cp.async.cg.shared.global [%0], [%1], 16;\n" :: "r"(s), "l"(gmem));
}
DI void cp_commit() { asm volatile("cp.async.commit_group;\n"); }
template <int N> DI void cp_wait() { asm volatile("cp.async.wait_group %0;\n" :: "n"(N)); }

DI uint32_t nz4(uint32_t w) {          // bit i = (byte i of w) != 0
    uint32_t r = 0;
    r |= (w & 0x000000FFu) ? 1u : 0u;
    r |= (w & 0x0000FF00u) ? 2u : 0u;
    r |= (w & 0x00FF0000u) ? 4u : 0u;
    r |= (w & 0xFF000000u) ? 8u : 0u;
    return r;
}

// ------- front kernel: converts + mask-dtype detect --------------------------
__global__ void conv_all(const float* __restrict__ keys, const float* __restrict__ values,
                         const float* __restrict__ Wk, const float* __restrict__ Wv,
                         const float* __restrict__ Wo, const uint32_t* __restrict__ mask) {
    const int bid = blockIdx.x;
    if (bid < 9728) {
        int i = bid * 256 + threadIdx.x;
        if (i < 1048576) {
            float4 v = reinterpret_cast<const float4*>(keys)[i];
            reinterpret_cast<uint2*>(g_kb)[i] = make_uint2(pack_bf16(v.x, v.y), pack_bf16(v.z, v.w));
        } else if (i < 2097152) {
            int j = i - 1048576;
            float4 v = reinterpret_cast<const float4*>(values)[j];
            reinterpret_cast<uint2*>(g_vb)[j] = make_uint2(pack_bf16(v.x, v.y), pack_bf16(v.z, v.w));
        } else if (i < 2228224) {
            int j = i - 2097152;
            float4 v = reinterpret_cast<const float4*>(Wk)[j];
            reinterpret_cast<uint2*>(g_wkb)[j] = make_uint2(pack_bf16(v.x, v.y), pack_bf16(v.z, v.w));
        } else if (i < 2359296) {
            int j = i - 2228224;
            float4 v = reinterpret_cast<const float4*>(Wv)[j];
            reinterpret_cast<uint2*>(g_wvb)[j] = make_uint2(pack_bf16(v.x, v.y), pack_bf16(v.z, v.w));
        } else if (i < 2490368) {
            int j = i - 2359296;
            int row = j >> 7, c4 = (j & 127) * 4;
            float4 v = *reinterpret_cast<const float4*>(Wo + (size_t)row * 1024 + c4);
            float4 r;
            r.x = __uint_as_float(f2tf32(v.x)); r.y = __uint_as_float(f2tf32(v.y));
            r.z = __uint_as_float(f2tf32(v.z)); r.w = __uint_as_float(f2tf32(v.w));
            *reinterpret_cast<float4*>(&g_wot[(size_t)row * 512 + c4]) = r;
        }
    } else {
        // detect: u8 vs 32-bit mask
        __shared__ int f;
        if (threadIdx.x == 0) f = 0;
        __syncthreads();
        int loc = 0;
        for (int i = threadIdx.x; i < 16384; i += 256) {
            uint32_t w = mask[i];
            if ((w & 0xFFFFFF00u) != 0u && w != 0x3F800000u) loc = 1;
        }
        if (loc) f = 1;
        __syncthreads();
        if (threadIdx.x == 0) g_mask_u8 = f;
    }
}

// ------- cvec: bo + v_sum @ Wo[:,512:1024].T (separate tiny launch) ----------
__global__ void cvec_kernel(const float* __restrict__ vsum,
                            const float* __restrict__ Wo,
                            const float* __restrict__ bo) {
    int w = blockIdx.x * 8 + (threadIdx.x >> 5);
    int lane = threadIdx.x & 31;
    float s = 0.0f;
    for (int j = lane; j < 512; j += 32)
        s += vsum[j] * Wo[(size_t)w * 1024 + 512 + j];
    #pragma unroll
    for (int o = 16; o; o >>= 1) s += __shfl_xor_sync(~0u, s, o);
    if (lane == 0) g_cvec[w] = s + bo[w];
}

// ---------------- gating GEMMs + co-scheduled mask repack --------------------
// blockIdx.z: 0 -> keys/Wk -> g_fk; 1 -> values/Wv -> g_fvT (transposed);
// z == 2 -> pure-DRAM mask->bitset repack CTAs, overlapped by the scheduler
// with the compute-bound gate CTAs (separate CTAs, no intra-CTA serialization).
__global__ __launch_bounds__(256) void gate_kernel(
    const float* __restrict__ bk, const float* __restrict__ kfb,
    const float* __restrict__ bv, const float* __restrict__ vfb,
    const uint8_t* __restrict__ Mask) {
    __shared__ __align__(16) __nv_bfloat16 Xs[2][128 * 40];
    __shared__ __align__(16) __nv_bfloat16 Ws[2][64 * 40];
    const int tid = threadIdx.x, warp = tid >> 5, lane = tid & 31;

    if (blockIdx.z == 2) {
        // repack: 256 blocks x 256 threads x 32 words; word gw == g_mbits index
        const int bid2 = blockIdx.x + 32 * blockIdx.y;   // 0..255
        const int mu8 = g_mask_u8;
        for (int i = 0; i < 32; i++) {
            int gw = bid2 * 8192 + i * 256 + tid;
            int bh = gw >> 17;                  // 2048*64 = 2^17 words per (b,h)
            int row = (gw >> 6) & 2047;
            int w = gw & 63;
            int bb = bh >> 3, hh = bh & 7;
            size_t ebase = ((size_t)(bb * 16 + hh) * 2048 + row) * 2048 + (size_t)w * 32;
            uint32_t bits = 0;
            if (mu8) {
                const uint4* p = reinterpret_cast<const uint4*>(Mask + ebase);
                uint4 a = __ldcs(p), c = __ldcs(p + 1);
                bits = nz4(a.x) | (nz4(a.y) << 4) | (nz4(a.z) << 8) | (nz4(a.w) << 12)
                     | (nz4(c.x) << 16) | (nz4(c.y) << 20) | (nz4(c.z) << 24) | (nz4(c.w) << 28);
            } else {
                const uint4* p = reinterpret_cast<const uint4*>(
                    reinterpret_cast<const uint32_t*>(Mask) + ebase);
                #pragma unroll
                for (int q = 0; q < 8; q++) {
                    uint4 v = __ldcs(p + q);
                    bits |= (v.x ? 1u : 0u) << (4 * q);
                    bits |= (v.y ? 1u : 0u) << (4 * q + 1);
                    bits |= (v.z ? 1u : 0u) << (4 * q + 2);
                    bits |= (v.w ? 1u : 0u) << (4 * q + 3);
                }
            }
            g_mbits[gw] = bits;
        }
        return;
    }

    const int gid = lane >> 2, t4 = lane & 3;
    const int m0 = blockIdx.x * 128, n0 = blockIdx.y * 64;
    const int which = blockIdx.z;
    const __nv_bfloat16* X = which ? g_vb : g_kb;
    const __nv_bfloat16* W = which ? g_wvb : g_wkb;
    const float* b1 = which ? bv : bk;
    const float* b2 = which ? vfb : kfb;
    float acc[8][4] = {};

    auto stage = [&](int bufi, int k0) {
        #pragma unroll
        for (int i = 0; i < 2; i++) {
            int c = tid + i * 256;
            int row = c >> 2, cc = (c & 3) * 16;
            cp_async16((char*)&Xs[bufi][0] + row * 80 + cc,
                       (const char*)(X + (size_t)(m0 + row) * 1024 + k0) + cc);
        }
        {   int row = tid >> 2, cc = (tid & 3) * 16;
            cp_async16((char*)&Ws[bufi][0] + row * 80 + cc,
                       (const char*)(W + (size_t)(n0 + row) * 1024 + k0) + cc);
        }
    };

    stage(0, 0); cp_commit();
    const int rowa = warp * 16 + gid;
    for (int kt = 0; kt < 32; kt++) {
        if (kt < 31) { stage((kt + 1) & 1, (kt + 1) * 32); cp_commit(); cp_wait<1>(); }
        else cp_wait<0>();
        __syncthreads();
        const uint32_t* Xw = reinterpret_cast<const uint32_t*>(&Xs[kt & 1][0]);
        const uint32_t* Ww = reinterpret_cast<const uint32_t*>(&Ws[kt & 1][0]);
        #pragma unroll
        for (int ks = 0; ks < 2; ks++) {
            uint32_t a0 = Xw[rowa * 20 + ks * 8 + t4];
            uint32_t a1 = Xw[(rowa + 8) * 20 + ks * 8 + t4];
            uint32_t a2 = Xw[rowa * 20 + ks * 8 + t4 + 4];
            uint32_t a3 = Xw[(rowa + 8) * 20 + ks * 8 + t4 + 4];
            #pragma unroll
            for (int j = 0; j < 8; j++) {
                mma_bf16(acc[j], a0, a1, a2, a3,
                         Ww[(j * 8 + gid) * 20 + ks * 8 + t4],
                         Ww[(j * 8 + gid) * 20 + ks * 8 + t4 + 4]);
            }
        }
        __syncthreads();
    }
    #pragma unroll
    for (int j = 0; j < 8; j++) {
        int col = n0 + j * 8 + t4 * 2;
        float bb0 = b1[col] + b2[col], bb1 = b1[col + 1] + b2[col + 1];
        float s0 = 1.0f / (1.0f + __expf(-(acc[j][0] + bb0)));
        float s1 = 1.0f / (1.0f + __expf(-(acc[j][1] + bb1)));
        float s2 = 1.0f / (1.0f + __expf(-(acc[j][2] + bb0)));
        float s3 = 1.0f / (1.0f + __expf(-(acc[j][3] + bb1)));
        if (which == 0) {
            *reinterpret_cast<uint32_t*>(&g_fk[(size_t)(m0 + rowa) * 512 + col]) = pack_bf16(s0, s1);
            *reinterpret_cast<uint32_t*>(&g_fk[(size_t)(m0 + rowa + 8) * 512 + col]) = pack_bf16(s2, s3);
        } else {
            g_fvT[(size_t)col * 4096 + m0 + rowa]           = __float2bfloat16(s0);
            g_fvT[(size_t)(col + 1) * 4096 + m0 + rowa]     = __float2bfloat16(s1);
            g_fvT[(size_t)col * 4096 + m0 + rowa + 8]       = __float2bfloat16(s2);
            g_fvT[(size_t)(col + 1) * 4096 + m0 + rowa + 8] = __float2bfloat16(s3);
        }
    }
}

// ---------------- flash attention, heads 0..7 (unchanged from R11) ----------
// smem: K 2x9216 | V 2x9216 | W 2x36864  = 110592 B
static constexpr int ATTN_SMEM = 110592;

__global__ __launch_bounds__(256, 2) void attn_kernel(
    const float* __restrict__ Q, const float* __restrict__ Wt) {
    extern __shared__ __align__(16) char dsm[];
    const int tid = threadIdx.x, warp = tid >> 5, lane = tid & 31;
    const int gid = lane >> 2, t4 = lane & 3;
    const int q0 = blockIdx.x * 128, h = blockIdx.y, b = blockIdx.z;
    const int bq = b * 2048;
    const int rowa = warp * 16 + gid;
    const int r0 = q0 + rowa, r1 = r0 + 8;

    uint32_t qa[4][4];
    {
        const float sc = 0.18033688f;   // (1/8) * log2(e)
        #pragma unroll
        for (int ks = 0; ks < 4; ks++) {
            const float* p0 = Q + (size_t)(bq + r0) * 1024 + h * 64 + ks * 16 + t4 * 2;
            const float* p1 = Q + (size_t)(bq + r1) * 1024 + h * 64 + ks * 16 + t4 * 2;
            float2 x0 = __ldcs(reinterpret_cast<const float2*>(p0));
            float2 x1 = __ldcs(reinterpret_cast<const float2*>(p1));
            float2 x2 = __ldcs(reinterpret_cast<const float2*>(p0 + 8));
            float2 x3 = __ldcs(reinterpret_cast<const float2*>(p1 + 8));
            qa[ks][0] = pack_bf16(x0.x * sc, x0.y * sc);
            qa[ks][1] = pack_bf16(x1.x * sc, x1.y * sc);
            qa[ks][2] = pack_bf16(x2.x * sc, x2.y * sc);
            qa[ks][3] = pack_bf16(x3.x * sc, x3.y * sc);
        }
    }

    const float* wtile = Wt + (size_t)(b * 16 + h) * 2048 * 2048 + (size_t)q0 * 2048;

    auto stage = [&](int buf, int kt) {
        const int k0 = kt * 64;
        char* kd = dsm + buf * 9216;
        char* vd = dsm + 18432 + buf * 9216;
        char* wd = dsm + 36864 + buf * 36864;
        #pragma unroll
        for (int i = 0; i < 2; i++) {
            int c = tid + i * 256;
            int r = c >> 3, cc = (c & 7) * 16;
            cp_async16(kd + r * 144 + cc,
                       (const char*)(g_fk + (size_t)(bq + k0 + r) * 512 + h * 64) + cc);
            cp_async16(vd + r * 144 + cc,
                       (const char*)(g_fvT + (size_t)(h * 64 + r) * 4096 + bq + k0) + cc);
        }
        #pragma unroll
        for (int i = 0; i < 8; i++) {
            int c = tid + i * 256;
            int r = c >> 4, sg = (c & 15) * 16;
            cp_async16(wd + r * 288 + sg,
                       (const char*)(wtile + (size_t)r * 2048 + k0) + sg);
        }
    };

    const uint32_t mb = (uint32_t)((((lane >> 4) * 8) + (lane & 7)) * 144 + ((lane >> 3) & 1) * 16);
    const uint32_t sbase = (uint32_t)__cvta_generic_to_shared(dsm);
    const uint32_t kS[2] = {sbase + mb, sbase + 9216 + mb};
    const uint32_t vS[2] = {sbase + 18432 + mb, sbase + 18432 + 9216 + mb};
    const char* const wg0 = dsm + 36864 + rowa * 288;
    const int toff = t4 * 8;

    float acc[8][4] = {};
    float lrow0 = 0.0f, lrow1 = 0.0f;
    const uint32_t* mp0 = g_mbits + ((size_t)(b * 8 + h) * 2048 + r0) * 64;
    const uint32_t* mp1 = g_mbits + ((size_t)(b * 8 + h) * 2048 + r1) * 64;

    stage(0, 0); cp_commit();
    for (int kt = 0; kt < 32; kt++) {
        const int cur = kt & 1;
        if (kt < 31) { stage(cur ^ 1, kt + 1); cp_commit(); cp_wait<1>(); }
        else cp_wait<0>();
        uint2 mw0 = __ldcs(reinterpret_cast<const uint2*>(mp0 + kt * 2));
        uint2 mw1 = __ldcs(reinterpret_cast<const uint2*>(mp1 + kt * 2));
        __syncthreads();
        const uint32_t kB = kS[cur], vB = vS[cur];
        const char* w0p = wg0 + cur * 36864;
        const char* w1p = w0p + 8 * 288;

        #pragma unroll
        for (int kk = 0; kk < 4; kk++) {
            const int j0 = 2 * kk, j1 = 2 * kk + 1;
            float s0[4] = {}, s1[4] = {};
            #pragma unroll
            for (int ks = 0; ks < 4; ks++) {
                uint32_t c0, c1, c2, c3;
                ldsm4(c0, c1, c2, c3, kB + (uint32_t)(kk * 2304 + ks * 32));
                mma_bf16(s0, qa[ks][0], qa[ks][1], qa[ks][2], qa[ks][3], c0, c1);
                mma_bf16(s1, qa[ks][0], qa[ks][1], qa[ks][2], qa[ks][3], c2, c3);
            }
            float2 w00 = *reinterpret_cast<const float2*>(w0p + j0 * 32 + toff);
            float2 w01 = *reinterpret_cast<const float2*>(w0p + j1 * 32 + toff);
            float2 w10 = *reinterpret_cast<const float2*>(w1p + j0 * 32 + toff);
            float2 w11 = *reinterpret_cast<const float2*>(w1p + j1 * 32 + toff);
            const int bit0 = (j0 * 8 + t4 * 2) & 31, bit1 = (j1 * 8 + t4 * 2) & 31;
            const uint32_t sel00 = (j0 < 4) ? mw0.x : mw0.y;
            const uint32_t sel01 = (j0 < 4) ? mw1.x : mw1.y;
            const uint32_t sel10 = (j1 < 4) ? mw0.x : mw0.y;
            const uint32_t sel11 = (j1 < 4) ? mw1.x : mw1.y;
            float p00 = ex2(s0[0] * w00.x), p01 = ex2(s0[1] * w00.y);
            float p02 = ex2(s0[2] * w10.x), p03 = ex2(s0[3] * w10.y);
            float p10 = ex2(s1[0] * w01.x), p11 = ex2(s1[1] * w01.y);
            float p12 = ex2(s1[2] * w11.x), p13 = ex2(s1[3] * w11.y);
            p00 = ((sel00 >> bit0) & 1)       ? 0.0f : p00;
            p01 = ((sel00 >> (bit0 + 1)) & 1) ? 0.0f : p01;
            p02 = ((sel01 >> bit0) & 1)       ? 0.0f : p02;
            p03 = ((sel01 >> (bit0 + 1)) & 1) ? 0.0f : p03;
            p10 = ((sel10 >> bit1) & 1)       ? 0.0f : p10;
            p11 = ((sel10 >> (bit1 + 1)) & 1) ? 0.0f : p11;
            p12 = ((sel11 >> bit1) & 1)       ? 0.0f : p12;
            p13 = ((sel11 >> (bit1 + 1)) & 1) ? 0.0f : p13;
            lrow0 += p00 + p01 + p10 + p11;
            lrow1 += p02 + p03 + p12 + p13;
            uint32_t a0 = pack_bf16(p00, p01), a1 = pack_bf16(p02, p03);
            uint32_t a2 = pack_bf16(p10, p11), a3 = pack_bf16(p12, p13);
            #pragma unroll
            for (int p = 0; p < 4; p++) {
                uint32_t c0, c1, c2, c3;
                ldsm4(c0, c1, c2, c3, vB + (uint32_t)(p * 2304 + kk * 32));
                mma_bf16(acc[2 * p],     a0, a1, a2, a3, c0, c1);
                mma_bf16(acc[2 * p + 1], a0, a1, a2, a3, c2, c3);
            }
        }
        __syncthreads();
    }
    lrow0 += __shfl_xor_sync(~0u, lrow0, 1); lrow0 += __shfl_xor_sync(~0u, lrow0, 2);
    lrow1 += __shfl_xor_sync(~0u, lrow1, 1); lrow1 += __shfl_xor_sync(~0u, lrow1, 2);
    float inv0 = 1.0f / lrow0, inv1 = 1.0f / lrow1;
    #pragma unroll
    for (int jg = 0; jg < 8; jg++) {
        int col = h * 64 + jg * 8 + t4 * 2;
        *reinterpret_cast<float2*>(&g_ao[(size_t)(bq + r0) * 512 + col]) =
            make_float2(__uint_as_float(f2tf32(acc[jg][0] * inv0)),
                        __uint_as_float(f2tf32(acc[jg][1] * inv0)));
        *reinterpret_cast<float2*>(&g_ao[(size_t)(bq + r1) * 512 + col]) =
            make_float2(__uint_as_float(f2tf32(acc[jg][2] * inv1)),
                        __uint_as_float(f2tf32(acc[jg][3] * inv1)));
    }
}

// ---------------- output projection (tf32, 128x64 tiles, double-buffered) ---
__global__ __launch_bounds__(256) void proj_kernel(float* __restrict__ out) {
    __shared__ __align__(16) float As[2][128 * 36];
    __shared__ __align__(16) float Bs[2][64 * 36];
    const int tid = threadIdx.x, warp = tid >> 5, lane = tid & 31;
    const int gid = lane >> 2, t4 = lane & 3;
    const int m0 = blockIdx.x * 128, n0 = blockIdx.y * 64;
    float acc[8][4] = {};

    auto stage = [&](int bufi, int k0) {
        #pragma unroll
        for (int i = 0; i < 4; i++) {            // A: 128 rows x 8 chunks
            int c = tid + i * 256;
            int row = c >> 3, cc = (c & 7) * 16;
            cp_async16((char*)&As[bufi][0] + row * 144 + cc,
                       (const char*)(g_ao + (size_t)(m0 + row) * 512 + k0) + cc);
        }
        #pragma unroll
        for (int i = 0; i < 2; i++) {            // B: 64 rows x 8 chunks
            int c = tid + i * 256;
            int row = c >> 3, cc = (c & 7) * 16;
            cp_async16((char*)&Bs[bufi][0] + row * 144 + cc,
                       (const char*)(g_wot + (size_t)(n0 + row) * 512 + k0) + cc);
        }
    };

    stage(0, 0); cp_commit();
    const int rowa = warp * 16 + gid;
    for (int kt = 0; kt < 16; kt++) {
        if (kt < 15) { stage((kt + 1) & 1, (kt + 1) * 32); cp_commit(); cp_wait<1>(); }
        else cp_wait<0>();
        __syncthreads();
        const uint32_t* Af = reinterpret_cast<const uint32_t*>(&As[kt & 1][0]);
        const uint32_t* Bf = reinterpret_cast<const uint32_t*>(&Bs[kt & 1][0]);
        #pragma unroll
        for (int ks = 0; ks < 4; ks++) {
            uint32_t a0 = Af[rowa * 36 + ks * 8 + t4];
            uint32_t a1 = Af[(rowa + 8) * 36 + ks * 8 + t4];
            uint32_t a2 = Af[rowa * 36 + ks * 8 + t4 + 4];
            uint32_t a3 = Af[(rowa + 8) * 36 + ks * 8 + t4 + 4];
            #pragma unroll
            for (int j = 0; j < 8; j++) {
                int nrow = j * 8 + gid;
                mma_tf32(acc[j], a0, a1, a2, a3,
                         Bf[nrow * 36 + ks * 8 + t4], Bf[nrow * 36 + ks * 8 + t4 + 4]);
            }
        }
        __syncthreads();
    }
    #pragma unroll
    for (int j = 0; j < 8; j++) {
        int col = n0 + j * 8 + t4 * 2;
        float c0 = g_cvec[col], c1 = g_cvec[col + 1];
        *reinterpret_cast<float2*>(out + (size_t)(m0 + rowa) * 1024 + col) =
            make_float2(acc[j][0] + c0, acc[j][1] + c1);
        *reinterpret_cast<float2*>(out + (size_t)(m0 + rowa + 8) * 1024 + col) =
            make_float2(acc[j][2] + c0, acc[j][3] + c1);
    }
}

extern "C" void kernel_launch(void* const* d_in, const int* in_sizes, int n_in,
                              void* d_out, int out_size) {
    (void)in_sizes; (void)n_in; (void)out_size;
    const float*   queries = (const float*)d_in[0];
    const float*   keys    = (const float*)d_in[1];
    const float*   values  = (const float*)d_in[2];
    const uint8_t* mask    = (const uint8_t*)d_in[3];
    const float*   weights = (const float*)d_in[4];
    const float*   Wk      = (const float*)d_in[5];
    const float*   bk      = (const float*)d_in[6];
    const float*   kfb     = (const float*)d_in[7];
    const float*   Wv      = (const float*)d_in[8];
    const float*   bv      = (const float*)d_in[9];
    const float*   vfb     = (const float*)d_in[10];
    // d_in[11] = k_sum: provably irrelevant (heads 8..15 output = v_sum)
    const float*   vsum    = (const float*)d_in[12];
    const float*   Wo      = (const float*)d_in[13];
    const float*   bo      = (const float*)d_in[14];
    float*         out     = (float*)d_out;

    cudaFuncSetAttribute(attn_kernel, cudaFuncAttributeMaxDynamicSharedMemorySize, ATTN_SMEM);

    conv_all<<<9729, 256>>>(keys, values, Wk, Wv, Wo, (const uint32_t*)mask); // idx 0
    gate_kernel<<<dim3(32, 8, 3), 256>>>(bk, kfb, bv, vfb, mask);             // idx 1 (gate + repack overlap)
    cvec_kernel<<<128, 256>>>(vsum, Wo, bo);                                  // idx 2
    attn_kernel<<<dim3(16, 8, 2), 256, ATTN_SMEM>>>(queries, weights);        // idx 3 (profiled)
    proj_kernel<<<dim3(32, 16), 256>>>(out);                                  // idx 4
}

// round 15
// speedup vs baseline: 1.0318x; 1.0318x over previous
#include <cuda_runtime.h>
#include <cuda_bf16.h>
#include <stdint.h>

#define DI __device__ __forceinline__

// Scratch (device globals: allocation-free contract)
__device__ __nv_bfloat16 g_kb[4096 * 1024];   // keys bf16
__device__ __nv_bfloat16 g_vb[4096 * 1024];   // values bf16
__device__ __nv_bfloat16 g_wkb[512 * 1024];   // Wk_f bf16
__device__ __nv_bfloat16 g_wvb[512 * 1024];   // Wv_f bf16
__device__ __align__(16) float g_wot[1024 * 512];  // Wo[:, :512] tf32-rounded
__device__ __nv_bfloat16 g_fk[4096 * 512];    // gated K halves [B*NK, 512]
__device__ __nv_bfloat16 g_fvT[512 * 4096];   // gated V halves, transposed
__device__ __align__(16) float g_ao[4096 * 512];   // attention out (tf32-rounded)
__device__ float         g_cvec[1024];        // bo + v_sum @ Wo[:,512:].T
__device__ __align__(16) uint32_t g_mbits[16 * 2048 * 64];  // mask bitset, heads 0..7
__device__ int           g_mask_u8;

DI uint32_t pack_bf16(float a, float b) {
    __nv_bfloat162 t = __floats2bfloat162_rn(a, b);
    return *reinterpret_cast<uint32_t*>(&t);
}
DI uint32_t f2tf32(float f) {
    uint32_t r;
    asm("cvt.rna.tf32.f32 %0, %1;" : "=r"(r) : "f"(f));
    return r;
}
DI float ex2(float x) {
    float r;
    asm("ex2.approx.f32 %0, %1;" : "=f"(r) : "f"(x));
    return r;
}
DI void mma_bf16(float* c, uint32_t a0, uint32_t a1, uint32_t a2, uint32_t a3,
                 uint32_t b0, uint32_t b1) {
    asm volatile(
        "mma.sync.aligned.m16n8k16.row.col.f32.bf16.bf16.f32 "
        "{%0,%1,%2,%3}, {%4,%5,%6,%7}, {%8,%9}, {%0,%1,%2,%3};\n"
        : "+f"(c[0]), "+f"(c[1]), "+f"(c[2]), "+f"(c[3])
        : "r"(a0), "r"(a1), "r"(a2), "r"(a3), "r"(b0), "r"(b1));
}
DI void mma_tf32(float* c, uint32_t a0, uint32_t a1, uint32_t a2, uint32_t a3,
                 uint32_t b0, uint32_t b1) {
    asm volatile(
        "mma.sync.aligned.m16n8k8.row.col.f32.tf32.tf32.f32 "
        "{%0,%1,%2,%3}, {%4,%5,%6,%7}, {%8,%9}, {%0,%1,%2,%3};\n"
        : "+f"(c[0]), "+f"(c[1]), "+f"(c[2]), "+f"(c[3])
        : "r"(a0), "r"(a1), "r"(a2), "r"(a3), "r"(b0), "r"(b1));
}
DI void ldsm4(uint32_t& r0, uint32_t& r1, uint32_t& r2, uint32_t& r3, uint32_t saddr) {
    asm volatile("ldmatrix.sync.aligned.m8n8.x4.shared.b16 {%0,%1,%2,%3}, [%4];"
                 : "=r"(r0), "=r"(r1), "=r"(r2), "=r"(r3) : "r"(saddr));
}
DI void cp_async16(void* smem, const void* gmem) {
    uint32_t s = (uint32_t)__cvta_generic_to_shared(smem);
    asm volatile("cp.async.cg.shared.global [%0], [%1], 16;\n" :: "r"(s), "l"(gmem));
}
DI void cp_commit() { asm volatile("cp.async.commit_group;\n"); }
template <int N> DI void cp_wait() { asm volatile("cp.async.wait_group %0;\n" :: "n"(N)); }

// ------- merged front kernel: converts + cvec + mask-dtype detect -----------
__global__ void conv_all(const float* __restrict__ keys, const float* __restrict__ values,
                         const float* __restrict__ Wk, const float* __restrict__ Wv,
                         const float* __restrict__ Wo, const float* __restrict__ vsum,
                         const float* __restrict__ bo, const uint32_t* __restrict__ mask) {
    const int bid = blockIdx.x;
    if (bid < 9728) {
        int i = bid * 256 + threadIdx.x;
        if (i < 1048576) {
            float4 v = reinterpret_cast<const float4*>(keys)[i];
            reinterpret_cast<uint2*>(g_kb)[i] = make_uint2(pack_bf16(v.x, v.y), pack_bf16(v.z, v.w));
        } else if (i < 2097152) {
            int j = i - 1048576;
            float4 v = reinterpret_cast<const float4*>(values)[j];
            reinterpret_cast<uint2*>(g_vb)[j] = make_uint2(pack_bf16(v.x, v.y), pack_bf16(v.z, v.w));
        } else if (i < 2228224) {
            int j = i - 2097152;
            float4 v = reinterpret_cast<const float4*>(Wk)[j];
            reinterpret_cast<uint2*>(g_wkb)[j] = make_uint2(pack_bf16(v.x, v.y), pack_bf16(v.z, v.w));
        } else if (i < 2359296) {
            int j = i - 2228224;
            float4 v = reinterpret_cast<const float4*>(Wv)[j];
            reinterpret_cast<uint2*>(g_wvb)[j] = make_uint2(pack_bf16(v.x, v.y), pack_bf16(v.z, v.w));
        } else if (i < 2490368) {
            int j = i - 2359296;
            int row = j >> 7, c4 = (j & 127) * 4;
            float4 v = *reinterpret_cast<const float4*>(Wo + (size_t)row * 1024 + c4);
            float4 r;
            r.x = __uint_as_float(f2tf32(v.x)); r.y = __uint_as_float(f2tf32(v.y));
            r.z = __uint_as_float(f2tf32(v.z)); r.w = __uint_as_float(f2tf32(v.w));
            *reinterpret_cast<float4*>(&g_wot[(size_t)row * 512 + c4]) = r;
        }
    } else if (bid < 9856) {
        int w = (bid - 9728) * 8 + (threadIdx.x >> 5);
        int lane = threadIdx.x & 31;
        float s = 0.0f;
        for (int j = lane; j < 512; j += 32)
            s += vsum[j] * Wo[(size_t)w * 1024 + 512 + j];
        #pragma unroll
        for (int o = 16; o; o >>= 1) s += __shfl_xor_sync(~0u, s, o);
        if (lane == 0) g_cvec[w] = s + bo[w];
    } else {
        __shared__ int f;
        if (threadIdx.x == 0) f = 0;
        __syncthreads();
        int loc = 0;
        for (int i = threadIdx.x; i < 16384; i += 256) {
            uint32_t w = mask[i];
            if ((w & 0xFFFFFF00u) != 0u && w != 0x3F800000u) loc = 1;
        }
        if (loc) f = 1;
        __syncthreads();
        if (threadIdx.x == 0) g_mask_u8 = f;
    }
}

// ---------------- mask -> bitset repack (heads 0..7 only) -------------------
__global__ void repack_kernel(const uint8_t* __restrict__ Mask) {
    const int warp = threadIdx.x >> 5, lane = threadIdx.x & 31;
    const int bh = blockIdx.y;
    const int row = blockIdx.x * 8 + warp;
    const int b = bh >> 3, h = bh & 7;
    const size_t base = ((size_t)(b * 16 + h) * 2048 + row) * 2048;
    uint32_t* dst = g_mbits + ((size_t)bh * 2048 + row) * 64;
    if (g_mask_u8) {
        #pragma unroll 4
        for (int w = 0; w < 64; w++) {
            int v = Mask[base + w * 32 + lane] != 0;
            uint32_t bits = __ballot_sync(~0u, v);
            if (lane == 0) dst[w] = bits;
        }
    } else {
        const uint32_t* M32 = reinterpret_cast<const uint32_t*>(Mask);
        #pragma unroll 4
        for (int w = 0; w < 64; w++) {
            int v = M32[base + w * 32 + lane] != 0u;
            uint32_t bits = __ballot_sync(~0u, v);
            if (lane == 0) dst[w] = bits;
        }
    }
}

// ---------------- gating GEMMs (merged, double-buffered) --------------------
__global__ __launch_bounds__(256) void gate_kernel(
    const float* __restrict__ bk, const float* __restrict__ kfb,
    const float* __restrict__ bv, const float* __restrict__ vfb) {
    __shared__ __align__(16) __nv_bfloat16 Xs[2][128 * 40];
    __shared__ __align__(16) __nv_bfloat16 Ws[2][64 * 40];
    const int tid = threadIdx.x, warp = tid >> 5, lane = tid & 31;
    const int gid = lane >> 2, t4 = lane & 3;
    const int m0 = blockIdx.x * 128, n0 = blockIdx.y * 64;
    const int which = blockIdx.z;
    const __nv_bfloat16* X = which ? g_vb : g_kb;
    const __nv_bfloat16* W = which ? g_wvb : g_wkb;
    const float* b1 = which ? bv : bk;
    const float* b2 = which ? vfb : kfb;
    float acc[8][4] = {};

    auto stage = [&](int bufi, int k0) {
        #pragma unroll
        for (int i = 0; i < 2; i++) {
            int c = tid + i * 256;
            int row = c >> 2, cc = (c & 3) * 16;
            cp_async16((char*)&Xs[bufi][0] + row * 80 + cc,
                       (const char*)(X + (size_t)(m0 + row) * 1024 + k0) + cc);
        }
        {   int row = tid >> 2, cc = (tid & 3) * 16;
            cp_async16((char*)&Ws[bufi][0] + row * 80 + cc,
                       (const char*)(W + (size_t)(n0 + row) * 1024 + k0) + cc);
        }
    };

    stage(0, 0); cp_commit();
    const int rowa = warp * 16 + gid;
    for (int kt = 0; kt < 32; kt++) {
        if (kt < 31) { stage((kt + 1) & 1, (kt + 1) * 32); cp_commit(); cp_wait<1>(); }
        else cp_wait<0>();
        __syncthreads();
        const uint32_t* Xw = reinterpret_cast<const uint32_t*>(&Xs[kt & 1][0]);
        const uint32_t* Ww = reinterpret_cast<const uint32_t*>(&Ws[kt & 1][0]);
        #pragma unroll
        for (int ks = 0; ks < 2; ks++) {
            uint32_t a0 = Xw[rowa * 20 + ks * 8 + t4];
            uint32_t a1 = Xw[(rowa + 8) * 20 + ks * 8 + t4];
            uint32_t a2 = Xw[rowa * 20 + ks * 8 + t4 + 4];
            uint32_t a3 = Xw[(rowa + 8) * 20 + ks * 8 + t4 + 4];
            #pragma unroll
            for (int j = 0; j < 8; j++) {
                mma_bf16(acc[j], a0, a1, a2, a3,
                         Ww[(j * 8 + gid) * 20 + ks * 8 + t4],
                         Ww[(j * 8 + gid) * 20 + ks * 8 + t4 + 4]);
            }
        }
        __syncthreads();
    }
    #pragma unroll
    for (int j = 0; j < 8; j++) {
        int col = n0 + j * 8 + t4 * 2;
        float bb0 = b1[col] + b2[col], bb1 = b1[col + 1] + b2[col + 1];
        float s0 = 1.0f / (1.0f + __expf(-(acc[j][0] + bb0)));
        float s1 = 1.0f / (1.0f + __expf(-(acc[j][1] + bb1)));
        float s2 = 1.0f / (1.0f + __expf(-(acc[j][2] + bb0)));
        float s3 = 1.0f / (1.0f + __expf(-(acc[j][3] + bb1)));
        if (which == 0) {
            *reinterpret_cast<uint32_t*>(&g_fk[(size_t)(m0 + rowa) * 512 + col]) = pack_bf16(s0, s1);
            *reinterpret_cast<uint32_t*>(&g_fk[(size_t)(m0 + rowa + 8) * 512 + col]) = pack_bf16(s2, s3);
        } else {
            g_fvT[(size_t)col * 4096 + m0 + rowa]           = __float2bfloat16(s0);
            g_fvT[(size_t)(col + 1) * 4096 + m0 + rowa]     = __float2bfloat16(s1);
            g_fvT[(size_t)col * 4096 + m0 + rowa + 8]       = __float2bfloat16(s2);
            g_fvT[(size_t)(col + 1) * 4096 + m0 + rowa + 8] = __float2bfloat16(s3);
        }
    }
}

// ---------------- flash attention, heads 0..7 (unchanged from R11) ----------
// smem: K 2x9216 | V 2x9216 | W 2x36864  = 110592 B
static constexpr int ATTN_SMEM = 110592;

__global__ __launch_bounds__(256, 2) void attn_kernel(
    const float* __restrict__ Q, const float* __restrict__ Wt) {
    extern __shared__ __align__(16) char dsm[];
    const int tid = threadIdx.x, warp = tid >> 5, lane = tid & 31;
    const int gid = lane >> 2, t4 = lane & 3;
    const int q0 = blockIdx.x * 128, h = blockIdx.y, b = blockIdx.z;
    const int bq = b * 2048;
    const int rowa = warp * 16 + gid;
    const int r0 = q0 + rowa, r1 = r0 + 8;

    uint32_t qa[4][4];
    {
        const float sc = 0.18033688f;   // (1/8) * log2(e)
        #pragma unroll
        for (int ks = 0; ks < 4; ks++) {
            const float* p0 = Q + (size_t)(bq + r0) * 1024 + h * 64 + ks * 16 + t4 * 2;
            const float* p1 = Q + (size_t)(bq + r1) * 1024 + h * 64 + ks * 16 + t4 * 2;
            float2 x0 = __ldcs(reinterpret_cast<const float2*>(p0));
            float2 x1 = __ldcs(reinterpret_cast<const float2*>(p1));
            float2 x2 = __ldcs(reinterpret_cast<const float2*>(p0 + 8));
            float2 x3 = __ldcs(reinterpret_cast<const float2*>(p1 + 8));
            qa[ks][0] = pack_bf16(x0.x * sc, x0.y * sc);
            qa[ks][1] = pack_bf16(x1.x * sc, x1.y * sc);
            qa[ks][2] = pack_bf16(x2.x * sc, x2.y * sc);
            qa[ks][3] = pack_bf16(x3.x * sc, x3.y * sc);
        }
    }

    const float* wtile = Wt + (size_t)(b * 16 + h) * 2048 * 2048 + (size_t)q0 * 2048;

    auto stage = [&](int buf, int kt) {
        const int k0 = kt * 64;
        char* kd = dsm + buf * 9216;
        char* vd = dsm + 18432 + buf * 9216;
        char* wd = dsm + 36864 + buf * 36864;
        #pragma unroll
        for (int i = 0; i < 2; i++) {
            int c = tid + i * 256;
            int r = c >> 3, cc = (c & 7) * 16;
            cp_async16(kd + r * 144 + cc,
                       (const char*)(g_fk + (size_t)(bq + k0 + r) * 512 + h * 64) + cc);
            cp_async16(vd + r * 144 + cc,
                       (const char*)(g_fvT + (size_t)(h * 64 + r) * 4096 + bq + k0) + cc);
        }
        #pragma unroll
        for (int i = 0; i < 8; i++) {
            int c = tid + i * 256;
            int r = c >> 4, sg = (c & 15) * 16;
            cp_async16(wd + r * 288 + sg,
                       (const char*)(wtile + (size_t)r * 2048 + k0) + sg);
        }
    };

    const uint32_t mb = (uint32_t)((((lane >> 4) * 8) + (lane & 7)) * 144 + ((lane >> 3) & 1) * 16);
    const uint32_t sbase = (uint32_t)__cvta_generic_to_shared(dsm);
    const uint32_t kS[2] = {sbase + mb, sbase + 9216 + mb};
    const uint32_t vS[2] = {sbase + 18432 + mb, sbase + 18432 + 9216 + mb};
    const char* const wg0 = dsm + 36864 + rowa * 288;
    const int toff = t4 * 8;

    float acc[8][4] = {};
    float lrow0 = 0.0f, lrow1 = 0.0f;
    const uint32_t* mp0 = g_mbits + ((size_t)(b * 8 + h) * 2048 + r0) * 64;
    const uint32_t* mp1 = g_mbits + ((size_t)(b * 8 + h) * 2048 + r1) * 64;

    stage(0, 0); cp_commit();
    for (int kt = 0; kt < 32; kt++) {
        const int cur = kt & 1;
        if (kt < 31) { stage(cur ^ 1, kt + 1); cp_commit(); cp_wait<1>(); }
        else cp_wait<0>();
        uint2 mw0 = __ldcs(reinterpret_cast<const uint2*>(mp0 + kt * 2));
        uint2 mw1 = __ldcs(reinterpret_cast<const uint2*>(mp1 + kt * 2));
        __syncthreads();
        const uint32_t kB = kS[cur], vB = vS[cur];
        const char* w0p = wg0 + cur * 36864;
        const char* w1p = w0p + 8 * 288;

        #pragma unroll
        for (int kk = 0; kk < 4; kk++) {
            const int j0 = 2 * kk, j1 = 2 * kk + 1;
            float s0[4] = {}, s1[4] = {};
            #pragma unroll
            for (int ks = 0; ks < 4; ks++) {
                uint32_t c0, c1, c2, c3;
                ldsm4(c0, c1, c2, c3, kB + (uint32_t)(kk * 2304 + ks * 32));
                mma_bf16(s0, qa[ks][0], qa[ks][1], qa[ks][2], qa[ks][3], c0, c1);
                mma_bf16(s1, qa[ks][0], qa[ks][1], qa[ks][2], qa[ks][3], c2, c3);
            }
            float2 w00 = *reinterpret_cast<const float2*>(w0p + j0 * 32 + toff);
            float2 w01 = *reinterpret_cast<const float2*>(w0p + j1 * 32 + toff);
            float2 w10 = *reinterpret_cast<const float2*>(w1p + j0 * 32 + toff);
            float2 w11 = *reinterpret_cast<const float2*>(w1p + j1 * 32 + toff);
            const int bit0 = (j0 * 8 + t4 * 2) & 31, bit1 = (j1 * 8 + t4 * 2) & 31;
            const uint32_t sel00 = (j0 < 4) ? mw0.x : mw0.y;
            const uint32_t sel01 = (j0 < 4) ? mw1.x : mw1.y;
            const uint32_t sel10 = (j1 < 4) ? mw0.x : mw0.y;
            const uint32_t sel11 = (j1 < 4) ? mw1.x : mw1.y;
            float p00 = ex2(s0[0] * w00.x), p01 = ex2(s0[1] * w00.y);
            float p02 = ex2(s0[2] * w10.x), p03 = ex2(s0[3] * w10.y);
            float p10 = ex2(s1[0] * w01.x), p11 = ex2(s1[1] * w01.y);
            float p12 = ex2(s1[2] * w11.x), p13 = ex2(s1[3] * w11.y);
            p00 = ((sel00 >> bit0) & 1)       ? 0.0f : p00;
            p01 = ((sel00 >> (bit0 + 1)) & 1) ? 0.0f : p01;
            p02 = ((sel01 >> bit0) & 1)       ? 0.0f : p02;
            p03 = ((sel01 >> (bit0 + 1)) & 1) ? 0.0f : p03;
            p10 = ((sel10 >> bit1) & 1)       ? 0.0f : p10;
            p11 = ((sel10 >> (bit1 + 1)) & 1) ? 0.0f : p11;
            p12 = ((sel11 >> bit1) & 1)       ? 0.0f : p12;
            p13 = ((sel11 >> (bit1 + 1)) & 1) ? 0.0f : p13;
            lrow0 += p00 + p01 + p10 + p11;
            lrow1 += p02 + p03 + p12 + p13;
            uint32_t a0 = pack_bf16(p00, p01), a1 = pack_bf16(p02, p03);
            uint32_t a2 = pack_bf16(p10, p11), a3 = pack_bf16(p12, p13);
            #pragma unroll
            for (int p = 0; p < 4; p++) {
                uint32_t c0, c1, c2, c3;
                ldsm4(c0, c1, c2, c3, vB + (uint32_t)(p * 2304 + kk * 32));
                mma_bf16(acc[2 * p],     a0, a1, a2, a3, c0, c1);
                mma_bf16(acc[2 * p + 1], a0, a1, a2, a3, c2, c3);
            }
        }
        __syncthreads();
    }
    lrow0 += __shfl_xor_sync(~0u, lrow0, 1); lrow0 += __shfl_xor_sync(~0u, lrow0, 2);
    lrow1 += __shfl_xor_sync(~0u, lrow1, 1); lrow1 += __shfl_xor_sync(~0u, lrow1, 2);
    float inv0 = 1.0f / lrow0, inv1 = 1.0f / lrow1;
    #pragma unroll
    for (int jg = 0; jg < 8; jg++) {
        int col = h * 64 + jg * 8 + t4 * 2;
        *reinterpret_cast<float2*>(&g_ao[(size_t)(bq + r0) * 512 + col]) =
            make_float2(__uint_as_float(f2tf32(acc[jg][0] * inv0)),
                        __uint_as_float(f2tf32(acc[jg][1] * inv0)));
        *reinterpret_cast<float2*>(&g_ao[(size_t)(bq + r1) * 512 + col]) =
            make_float2(__uint_as_float(f2tf32(acc[jg][2] * inv1)),
                        __uint_as_float(f2tf32(acc[jg][3] * inv1)));
    }
}

// ---------------- output projection (tf32, 128x64 tiles, double-buffered) ---
__global__ __launch_bounds__(256) void proj_kernel(float* __restrict__ out) {
    __shared__ __align__(16) float As[2][128 * 36];
    __shared__ __align__(16) float Bs[2][64 * 36];
    const int tid = threadIdx.x, warp = tid >> 5, lane = tid & 31;
    const int gid = lane >> 2, t4 = lane & 3;
    const int m0 = blockIdx.x * 128, n0 = blockIdx.y * 64;
    float acc[8][4] = {};

    auto stage = [&](int bufi, int k0) {
        #pragma unroll
        for (int i = 0; i < 4; i++) {            // A: 128 rows x 8 chunks
            int c = tid + i * 256;
            int row = c >> 3, cc = (c & 7) * 16;
            cp_async16((char*)&As[bufi][0] + row * 144 + cc,
                       (const char*)(g_ao + (size_t)(m0 + row) * 512 + k0) + cc);
        }
        #pragma unroll
        for (int i = 0; i < 2; i++) {            // B: 64 rows x 8 chunks
            int c = tid + i * 256;
            int row = c >> 3, cc = (c & 7) * 16;
            cp_async16((char*)&Bs[bufi][0] + row * 144 + cc,
                       (const char*)(g_wot + (size_t)(n0 + row) * 512 + k0) + cc);
        }
    };

    stage(0, 0); cp_commit();
    const int rowa = warp * 16 + gid;
    for (int kt = 0; kt < 16; kt++) {
        if (kt < 15) { stage((kt + 1) & 1, (kt + 1) * 32); cp_commit(); cp_wait<1>(); }
        else cp_wait<0>();
        __syncthreads();
        const uint32_t* Af = reinterpret_cast<const uint32_t*>(&As[kt & 1][0]);
        const uint32_t* Bf = reinterpret_cast<const uint32_t*>(&Bs[kt & 1][0]);
        #pragma unroll
        for (int ks = 0; ks < 4; ks++) {
            uint32_t a0 = Af[rowa * 36 + ks * 8 + t4];
            uint32_t a1 = Af[(rowa + 8) * 36 + ks * 8 + t4];
            uint32_t a2 = Af[rowa * 36 + ks * 8 + t4 + 4];
            uint32_t a3 = Af[(rowa + 8) * 36 + ks * 8 + t4 + 4];
            #pragma unroll
            for (int j = 0; j < 8; j++) {
                int nrow = j * 8 + gid;
                mma_tf32(acc[j], a0, a1, a2, a3,
                         Bf[nrow * 36 + ks * 8 + t4], Bf[nrow * 36 + ks * 8 + t4 + 4]);
            }
        }
        __syncthreads();
    }
    #pragma unroll
    for (int j = 0; j < 8; j++) {
        int col = n0 + j * 8 + t4 * 2;
        float c0 = g_cvec[col], c1 = g_cvec[col + 1];
        *reinterpret_cast<float2*>(out + (size_t)(m0 + rowa) * 1024 + col) =
            make_float2(acc[j][0] + c0, acc[j][1] + c1);
        *reinterpret_cast<float2*>(out + (size_t)(m0 + rowa + 8) * 1024 + col) =
            make_float2(acc[j][2] + c0, acc[j][3] + c1);
    }
}

extern "C" void kernel_launch(void* const* d_in, const int* in_sizes, int n_in,
                              void* d_out, int out_size) {
    (void)in_sizes; (void)n_in; (void)out_size;
    const float*   queries = (const float*)d_in[0];
    const float*   keys    = (const float*)d_in[1];
    const float*   values  = (const float*)d_in[2];
    const uint8_t* mask    = (const uint8_t*)d_in[3];
    const float*   weights = (const float*)d_in[4];
    const float*   Wk      = (const float*)d_in[5];
    const float*   bk      = (const float*)d_in[6];
    const float*   kfb     = (const float*)d_in[7];
    const float*   Wv      = (const float*)d_in[8];
    const float*   bv      = (const float*)d_in[9];
    const float*   vfb     = (const float*)d_in[10];
    // d_in[11] = k_sum: provably irrelevant (heads 8..15 output = v_sum)
    const float*   vsum    = (const float*)d_in[12];
    const float*   Wo      = (const float*)d_in[13];
    const float*   bo      = (const float*)d_in[14];
    float*         out     = (float*)d_out;

    cudaFuncSetAttribute(attn_kernel, cudaFuncAttributeMaxDynamicSharedMemorySize, ATTN_SMEM);

    conv_all<<<9857, 256>>>(keys, values, Wk, Wv, Wo, vsum, bo,
                            (const uint32_t*)mask);                   // idx 0
    repack_kernel<<<dim3(256, 16), 256>>>(mask);                      // idx 1
    gate_kernel<<<dim3(32, 8, 2), 256>>>(bk, kfb, bv, vfb);           // idx 2
    attn_kernel<<<dim3(16, 8, 2), 256, ATTN_SMEM>>>(queries, weights);// idx 3 (profiled)
    proj_kernel<<<dim3(32, 16), 256>>>(out);                          // idx 4
}

// round 16
// speedup vs baseline: 1.0455x; 1.0133x over previous
#include <cuda_runtime.h>
#include <cuda_bf16.h>
#include <stdint.h>

#define DI __device__ __forceinline__

// Scratch (device globals: allocation-free contract)
__device__ __nv_bfloat16 g_kb[4096 * 1024];   // keys bf16
__device__ __nv_bfloat16 g_vb[4096 * 1024];   // values bf16
__device__ __nv_bfloat16 g_wkb[512 * 1024];   // Wk_f bf16
__device__ __nv_bfloat16 g_wvb[512 * 1024];   // Wv_f bf16
__device__ __align__(16) float g_wot[1024 * 512];  // Wo[:, :512] tf32-rounded
__device__ __nv_bfloat16 g_fk[4096 * 512];    // gated K halves [B*NK, 512]
__device__ __nv_bfloat16 g_fvT[512 * 4096];   // gated V halves, transposed
__device__ __align__(16) float g_ao[4096 * 512];   // attention out (tf32-rounded)
__device__ float         g_cvec[1024];        // bo + v_sum @ Wo[:,512:].T
__device__ __align__(16) uint32_t g_mbits[16 * 2048 * 64];  // mask bitset, heads 0..7
__device__ int           g_mask_u8;

DI uint32_t pack_bf16(float a, float b) {
    __nv_bfloat162 t = __floats2bfloat162_rn(a, b);
    return *reinterpret_cast<uint32_t*>(&t);
}
DI uint32_t f2tf32(float f) {
    uint32_t r;
    asm("cvt.rna.tf32.f32 %0, %1;" : "=r"(r) : "f"(f));
    return r;
}
DI float ex2(float x) {
    float r;
    asm("ex2.approx.f32 %0, %1;" : "=f"(r) : "f"(x));
    return r;
}
DI void mma_bf16(float* c, uint32_t a0, uint32_t a1, uint32_t a2, uint32_t a3,
                 uint32_t b0, uint32_t b1) {
    asm volatile(
        "mma.sync.aligned.m16n8k16.row.col.f32.bf16.bf16.f32 "
        "{%0,%1,%2,%3}, {%4,%5,%6,%7}, {%8,%9}, {%0,%1,%2,%3};\n"
        : "+f"(c[0]), "+f"(c[1]), "+f"(c[2]), "+f"(c[3])
        : "r"(a0), "r"(a1), "r"(a2), "r"(a3), "r"(b0), "r"(b1));
}
DI void mma_tf32(float* c, uint32_t a0, uint32_t a1, uint32_t a2, uint32_t a3,
                 uint32_t b0, uint32_t b1) {
    asm volatile(
        "mma.sync.aligned.m16n8k8.row.col.f32.tf32.tf32.f32 "
        "{%0,%1,%2,%3}, {%4,%5,%6,%7}, {%8,%9}, {%0,%1,%2,%3};\n"
        : "+f"(c[0]), "+f"(c[1]), "+f"(c[2]), "+f"(c[3])
        : "r"(a0), "r"(a1), "r"(a2), "r"(a3), "r"(b0), "r"(b1));
}
DI void ldsm4(uint32_t& r0, uint32_t& r1, uint32_t& r2, uint32_t& r3, uint32_t saddr) {
    asm volatile("ldmatrix.sync.aligned.m8n8.x4.shared.b16 {%0,%1,%2,%3}, [%4];"
                 : "=r"(r0), "=r"(r1), "=r"(r2), "=r"(r3) : "r"(saddr));
}
DI void cp_async16(void* smem, const void* gmem) {
    uint32_t s = (uint32_t)__cvta_generic_to_shared(smem);
    asm volatile("cp.async.cg.shared.global [%0], [%1], 16;\n" :: "r"(s), "l"(gmem));
}
DI void cp_commit() { asm volatile("cp.async.commit_group;\n"); }
template <int N> DI void cp_wait() { asm volatile("cp.async.wait_group %0;\n" :: "n"(N)); }

// ------- detect: u8 vs 32-bit mask (tiny, must precede front_kernel) --------
__global__ void detect_kernel(const uint32_t* __restrict__ m) {
    __shared__ int f;
    if (threadIdx.x == 0) f = 0;
    __syncthreads();
    int loc = 0;
    for (int i = threadIdx.x; i < 16384; i += 256) {
        uint32_t w = m[i];
        if ((w & 0xFFFFFF00u) != 0u && w != 0x3F800000u) loc = 1;
    }
    if (loc) f = 1;
    __syncthreads();
    if (threadIdx.x == 0) g_mask_u8 = f;
}

// ------- merged front kernel: mask repack + converts + cvec -----------------
// All branches are DRAM-bound streams; merging lets the 268 MB mask read
// overlap the 68 MB convert traffic in one grid. Repack blocks first.
__global__ void front_kernel(const float* __restrict__ keys, const float* __restrict__ values,
                             const float* __restrict__ Wk, const float* __restrict__ Wv,
                             const float* __restrict__ Wo, const float* __restrict__ vsum,
                             const float* __restrict__ bo, const uint8_t* __restrict__ Mask) {
    const int bid = blockIdx.x;
    if (bid < 4096) {
        // ---- mask -> bitset repack (heads 0..7): one warp per mask row ----
        const int warp = threadIdx.x >> 5, lane = threadIdx.x & 31;
        const int bh = bid >> 8;                    // 0..15 -> (b, h<8)
        const int row = (bid & 255) * 8 + warp;
        const int b = bh >> 3, h = bh & 7;
        const size_t base = ((size_t)(b * 16 + h) * 2048 + row) * 2048;
        uint32_t* dst = g_mbits + ((size_t)bh * 2048 + row) * 64;
        if (g_mask_u8) {
            #pragma unroll 4
            for (int w = 0; w < 64; w++) {
                int v = Mask[base + w * 32 + lane] != 0;
                uint32_t bits = __ballot_sync(~0u, v);
                if (lane == 0) dst[w] = bits;
            }
        } else {
            const uint32_t* M32 = reinterpret_cast<const uint32_t*>(Mask);
            #pragma unroll 4
            for (int w = 0; w < 64; w++) {
                int v = M32[base + w * 32 + lane] != 0u;
                uint32_t bits = __ballot_sync(~0u, v);
                if (lane == 0) dst[w] = bits;
            }
        }
    } else if (bid < 13824) {
        // ---- converts: keys/values/Wk/Wv -> bf16, Wo[:, :512] -> tf32 -----
        int i = (bid - 4096) * 256 + threadIdx.x;
        if (i < 1048576) {
            float4 v = reinterpret_cast<const float4*>(keys)[i];
            reinterpret_cast<uint2*>(g_kb)[i] = make_uint2(pack_bf16(v.x, v.y), pack_bf16(v.z, v.w));
        } else if (i < 2097152) {
            int j = i - 1048576;
            float4 v = reinterpret_cast<const float4*>(values)[j];
            reinterpret_cast<uint2*>(g_vb)[j] = make_uint2(pack_bf16(v.x, v.y), pack_bf16(v.z, v.w));
        } else if (i < 2228224) {
            int j = i - 2097152;
            float4 v = reinterpret_cast<const float4*>(Wk)[j];
            reinterpret_cast<uint2*>(g_wkb)[j] = make_uint2(pack_bf16(v.x, v.y), pack_bf16(v.z, v.w));
        } else if (i < 2359296) {
            int j = i - 2228224;
            float4 v = reinterpret_cast<const float4*>(Wv)[j];
            reinterpret_cast<uint2*>(g_wvb)[j] = make_uint2(pack_bf16(v.x, v.y), pack_bf16(v.z, v.w));
        } else if (i < 2490368) {
            int j = i - 2359296;
            int row = j >> 7, c4 = (j & 127) * 4;
            float4 v = *reinterpret_cast<const float4*>(Wo + (size_t)row * 1024 + c4);
            float4 r;
            r.x = __uint_as_float(f2tf32(v.x)); r.y = __uint_as_float(f2tf32(v.y));
            r.z = __uint_as_float(f2tf32(v.z)); r.w = __uint_as_float(f2tf32(v.w));
            *reinterpret_cast<float4*>(&g_wot[(size_t)row * 512 + c4]) = r;
        }
    } else {
        // ---- cvec: bo + v_sum @ Wo[:,512:1024].T (one warp per column) ----
        int w = (bid - 13824) * 8 + (threadIdx.x >> 5);
        int lane = threadIdx.x & 31;
        float s = 0.0f;
        for (int j = lane; j < 512; j += 32)
            s += vsum[j] * Wo[(size_t)w * 1024 + 512 + j];
        #pragma unroll
        for (int o = 16; o; o >>= 1) s += __shfl_xor_sync(~0u, s, o);
        if (lane == 0) g_cvec[w] = s + bo[w];
    }
}

// ---------------- gating GEMMs (merged, double-buffered) --------------------
__global__ __launch_bounds__(256) void gate_kernel(
    const float* __restrict__ bk, const float* __restrict__ kfb,
    const float* __restrict__ bv, const float* __restrict__ vfb) {
    __shared__ __align__(16) __nv_bfloat16 Xs[2][128 * 40];
    __shared__ __align__(16) __nv_bfloat16 Ws[2][64 * 40];
    const int tid = threadIdx.x, warp = tid >> 5, lane = tid & 31;
    const int gid = lane >> 2, t4 = lane & 3;
    const int m0 = blockIdx.x * 128, n0 = blockIdx.y * 64;
    const int which = blockIdx.z;
    const __nv_bfloat16* X = which ? g_vb : g_kb;
    const __nv_bfloat16* W = which ? g_wvb : g_wkb;
    const float* b1 = which ? bv : bk;
    const float* b2 = which ? vfb : kfb;
    float acc[8][4] = {};

    auto stage = [&](int bufi, int k0) {
        #pragma unroll
        for (int i = 0; i < 2; i++) {
            int c = tid + i * 256;
            int row = c >> 2, cc = (c & 3) * 16;
            cp_async16((char*)&Xs[bufi][0] + row * 80 + cc,
                       (const char*)(X + (size_t)(m0 + row) * 1024 + k0) + cc);
        }
        {   int row = tid >> 2, cc = (tid & 3) * 16;
            cp_async16((char*)&Ws[bufi][0] + row * 80 + cc,
                       (const char*)(W + (size_t)(n0 + row) * 1024 + k0) + cc);
        }
    };

    stage(0, 0); cp_commit();
    const int rowa = warp * 16 + gid;
    for (int kt = 0; kt < 32; kt++) {
        if (kt < 31) { stage((kt + 1) & 1, (kt + 1) * 32); cp_commit(); cp_wait<1>(); }
        else cp_wait<0>();
        __syncthreads();
        const uint32_t* Xw = reinterpret_cast<const uint32_t*>(&Xs[kt & 1][0]);
        const uint32_t* Ww = reinterpret_cast<const uint32_t*>(&Ws[kt & 1][0]);
        #pragma unroll
        for (int ks = 0; ks < 2; ks++) {
            uint32_t a0 = Xw[rowa * 20 + ks * 8 + t4];
            uint32_t a1 = Xw[(rowa + 8) * 20 + ks * 8 + t4];
            uint32_t a2 = Xw[rowa * 20 + ks * 8 + t4 + 4];
            uint32_t a3 = Xw[(rowa + 8) * 20 + ks * 8 + t4 + 4];
            #pragma unroll
            for (int j = 0; j < 8; j++) {
                mma_bf16(acc[j], a0, a1, a2, a3,
                         Ww[(j * 8 + gid) * 20 + ks * 8 + t4],
                         Ww[(j * 8 + gid) * 20 + ks * 8 + t4 + 4]);
            }
        }
        __syncthreads();
    }
    #pragma unroll
    for (int j = 0; j < 8; j++) {
        int col = n0 + j * 8 + t4 * 2;
        float bb0 = b1[col] + b2[col], bb1 = b1[col + 1] + b2[col + 1];
        float s0 = 1.0f / (1.0f + __expf(-(acc[j][0] + bb0)));
        float s1 = 1.0f / (1.0f + __expf(-(acc[j][1] + bb1)));
        float s2 = 1.0f / (1.0f + __expf(-(acc[j][2] + bb0)));
        float s3 = 1.0f / (1.0f + __expf(-(acc[j][3] + bb1)));
        if (which == 0) {
            *reinterpret_cast<uint32_t*>(&g_fk[(size_t)(m0 + rowa) * 512 + col]) = pack_bf16(s0, s1);
            *reinterpret_cast<uint32_t*>(&g_fk[(size_t)(m0 + rowa + 8) * 512 + col]) = pack_bf16(s2, s3);
        } else {
            g_fvT[(size_t)col * 4096 + m0 + rowa]           = __float2bfloat16(s0);
            g_fvT[(size_t)(col + 1) * 4096 + m0 + rowa]     = __float2bfloat16(s1);
            g_fvT[(size_t)col * 4096 + m0 + rowa + 8]       = __float2bfloat16(s2);
            g_fvT[(size_t)(col + 1) * 4096 + m0 + rowa + 8] = __float2bfloat16(s3);
        }
    }
}

// ---------------- flash attention, heads 0..7 (unchanged) -------------------
// smem: K 2x9216 | V 2x9216 | W 2x36864  = 110592 B
static constexpr int ATTN_SMEM = 110592;

__global__ __launch_bounds__(256, 2) void attn_kernel(
    const float* __restrict__ Q, const float* __restrict__ Wt) {
    extern __shared__ __align__(16) char dsm[];
    const int tid = threadIdx.x, warp = tid >> 5, lane = tid & 31;
    const int gid = lane >> 2, t4 = lane & 3;
    const int q0 = blockIdx.x * 128, h = blockIdx.y, b = blockIdx.z;
    const int bq = b * 2048;
    const int rowa = warp * 16 + gid;
    const int r0 = q0 + rowa, r1 = r0 + 8;

    uint32_t qa[4][4];
    {
        const float sc = 0.18033688f;   // (1/8) * log2(e)
        #pragma unroll
        for (int ks = 0; ks < 4; ks++) {
            const float* p0 = Q + (size_t)(bq + r0) * 1024 + h * 64 + ks * 16 + t4 * 2;
            const float* p1 = Q + (size_t)(bq + r1) * 1024 + h * 64 + ks * 16 + t4 * 2;
            float2 x0 = __ldcs(reinterpret_cast<const float2*>(p0));
            float2 x1 = __ldcs(reinterpret_cast<const float2*>(p1));
            float2 x2 = __ldcs(reinterpret_cast<const float2*>(p0 + 8));
            float2 x3 = __ldcs(reinterpret_cast<const float2*>(p1 + 8));
            qa[ks][0] = pack_bf16(x0.x * sc, x0.y * sc);
            qa[ks][1] = pack_bf16(x1.x * sc, x1.y * sc);
            qa[ks][2] = pack_bf16(x2.x * sc, x2.y * sc);
            qa[ks][3] = pack_bf16(x3.x * sc, x3.y * sc);
        }
    }

    const float* wtile = Wt + (size_t)(b * 16 + h) * 2048 * 2048 + (size_t)q0 * 2048;

    auto stage = [&](int buf, int kt) {
        const int k0 = kt * 64;
        char* kd = dsm + buf * 9216;
        char* vd = dsm + 18432 + buf * 9216;
        char* wd = dsm + 36864 + buf * 36864;
        #pragma unroll
        for (int i = 0; i < 2; i++) {
            int c = tid + i * 256;
            int r = c >> 3, cc = (c & 7) * 16;
            cp_async16(kd + r * 144 + cc,
                       (const char*)(g_fk + (size_t)(bq + k0 + r) * 512 + h * 64) + cc);
            cp_async16(vd + r * 144 + cc,
                       (const char*)(g_fvT + (size_t)(h * 64 + r) * 4096 + bq + k0) + cc);
        }
        #pragma unroll
        for (int i = 0; i < 8; i++) {
            int c = tid + i * 256;
            int r = c >> 4, sg = (c & 15) * 16;
            cp_async16(wd + r * 288 + sg,
                       (const char*)(wtile + (size_t)r * 2048 + k0) + sg);
        }
    };

    const uint32_t mb = (uint32_t)((((lane >> 4) * 8) + (lane & 7)) * 144 + ((lane >> 3) & 1) * 16);
    const uint32_t sbase = (uint32_t)__cvta_generic_to_shared(dsm);
    const uint32_t kS[2] = {sbase + mb, sbase + 9216 + mb};
    const uint32_t vS[2] = {sbase + 18432 + mb, sbase + 18432 + 9216 + mb};
    const char* const wg0 = dsm + 36864 + rowa * 288;
    const int toff = t4 * 8;

    float acc[8][4] = {};
    float lrow0 = 0.0f, lrow1 = 0.0f;
    const uint32_t* mp0 = g_mbits + ((size_t)(b * 8 + h) * 2048 + r0) * 64;
    const uint32_t* mp1 = g_mbits + ((size_t)(b * 8 + h) * 2048 + r1) * 64;

    stage(0, 0); cp_commit();
    for (int kt = 0; kt < 32; kt++) {
        const int cur = kt & 1;
        if (kt < 31) { stage(cur ^ 1, kt + 1); cp_commit(); cp_wait<1>(); }
        else cp_wait<0>();
        uint2 mw0 = __ldcs(reinterpret_cast<const uint2*>(mp0 + kt * 2));
        uint2 mw1 = __ldcs(reinterpret_cast<const uint2*>(mp1 + kt * 2));
        __syncthreads();
        const uint32_t kB = kS[cur], vB = vS[cur];
        const char* w0p = wg0 + cur * 36864;
        const char* w1p = w0p + 8 * 288;

        #pragma unroll
        for (int kk = 0; kk < 4; kk++) {
            const int j0 = 2 * kk, j1 = 2 * kk + 1;
            float s0[4] = {}, s1[4] = {};
            #pragma unroll
            for (int ks = 0; ks < 4; ks++) {
                uint32_t c0, c1, c2, c3;
                ldsm4(c0, c1, c2, c3, kB + (uint32_t)(kk * 2304 + ks * 32));
                mma_bf16(s0, qa[ks][0], qa[ks][1], qa[ks][2], qa[ks][3], c0, c1);
                mma_bf16(s1, qa[ks][0], qa[ks][1], qa[ks][2], qa[ks][3], c2, c3);
            }
            float2 w00 = *reinterpret_cast<const float2*>(w0p + j0 * 32 + toff);
            float2 w01 = *reinterpret_cast<const float2*>(w0p + j1 * 32 + toff);
            float2 w10 = *reinterpret_cast<const float2*>(w1p + j0 * 32 + toff);
            float2 w11 = *reinterpret_cast<const float2*>(w1p + j1 * 32 + toff);
            const int bit0 = (j0 * 8 + t4 * 2) & 31, bit1 = (j1 * 8 + t4 * 2) & 31;
            const uint32_t sel00 = (j0 < 4) ? mw0.x : mw0.y;
            const uint32_t sel01 = (j0 < 4) ? mw1.x : mw1.y;
            const uint32_t sel10 = (j1 < 4) ? mw0.x : mw0.y;
            const uint32_t sel11 = (j1 < 4) ? mw1.x : mw1.y;
            float p00 = ex2(s0[0] * w00.x), p01 = ex2(s0[1] * w00.y);
            float p02 = ex2(s0[2] * w10.x), p03 = ex2(s0[3] * w10.y);
            float p10 = ex2(s1[0] * w01.x), p11 = ex2(s1[1] * w01.y);
            float p12 = ex2(s1[2] * w11.x), p13 = ex2(s1[3] * w11.y);
            p00 = ((sel00 >> bit0) & 1)       ? 0.0f : p00;
            p01 = ((sel00 >> (bit0 + 1)) & 1) ? 0.0f : p01;
            p02 = ((sel01 >> bit0) & 1)       ? 0.0f : p02;
            p03 = ((sel01 >> (bit0 + 1)) & 1) ? 0.0f : p03;
            p10 = ((sel10 >> bit1) & 1)       ? 0.0f : p10;
            p11 = ((sel10 >> (bit1 + 1)) & 1) ? 0.0f : p11;
            p12 = ((sel11 >> bit1) & 1)       ? 0.0f : p12;
            p13 = ((sel11 >> (bit1 + 1)) & 1) ? 0.0f : p13;
            lrow0 += p00 + p01 + p10 + p11;
            lrow1 += p02 + p03 + p12 + p13;
            uint32_t a0 = pack_bf16(p00, p01), a1 = pack_bf16(p02, p03);
            uint32_t a2 = pack_bf16(p10, p11), a3 = pack_bf16(p12, p13);
            #pragma unroll
            for (int p = 0; p < 4; p++) {
                uint32_t c0, c1, c2, c3;
                ldsm4(c0, c1, c2, c3, vB + (uint32_t)(p * 2304 + kk * 32));
                mma_bf16(acc[2 * p],     a0, a1, a2, a3, c0, c1);
                mma_bf16(acc[2 * p + 1], a0, a1, a2, a3, c2, c3);
            }
        }
        __syncthreads();
    }
    lrow0 += __shfl_xor_sync(~0u, lrow0, 1); lrow0 += __shfl_xor_sync(~0u, lrow0, 2);
    lrow1 += __shfl_xor_sync(~0u, lrow1, 1); lrow1 += __shfl_xor_sync(~0u, lrow1, 2);
    float inv0 = 1.0f / lrow0, inv1 = 1.0f / lrow1;
    #pragma unroll
    for (int jg = 0; jg < 8; jg++) {
        int col = h * 64 + jg * 8 + t4 * 2;
        *reinterpret_cast<float2*>(&g_ao[(size_t)(bq + r0) * 512 + col]) =
            make_float2(__uint_as_float(f2tf32(acc[jg][0] * inv0)),
                        __uint_as_float(f2tf32(acc[jg][1] * inv0)));
        *reinterpret_cast<float2*>(&g_ao[(size_t)(bq + r1) * 512 + col]) =
            make_float2(__uint_as_float(f2tf32(acc[jg][2] * inv1)),
                        __uint_as_float(f2tf32(acc[jg][3] * inv1)));
    }
}

// ---------------- output projection (tf32, 128x64 tiles, double-buffered) ---
__global__ __launch_bounds__(256) void proj_kernel(float* __restrict__ out) {
    __shared__ __align__(16) float As[2][128 * 36];
    __shared__ __align__(16) float Bs[2][64 * 36];
    const int tid = threadIdx.x, warp = tid >> 5, lane = tid & 31;
    const int gid = lane >> 2, t4 = lane & 3;
    const int m0 = blockIdx.x * 128, n0 = blockIdx.y * 64;
    float acc[8][4] = {};

    auto stage = [&](int bufi, int k0) {
        #pragma unroll
        for (int i = 0; i < 4; i++) {
            int c = tid + i * 256;
            int row = c >> 3, cc = (c & 7) * 16;
            cp_async16((char*)&As[bufi][0] + row * 144 + cc,
                       (const char*)(g_ao + (size_t)(m0 + row) * 512 + k0) + cc);
        }
        #pragma unroll
        for (int i = 0; i < 2; i++) {
            int c = tid + i * 256;
            int row = c >> 3, cc = (c & 7) * 16;
            cp_async16((char*)&Bs[bufi][0] + row * 144 + cc,
                       (const char*)(g_wot + (size_t)(n0 + row) * 512 + k0) + cc);
        }
    };

    stage(0, 0); cp_commit();
    const int rowa = warp * 16 + gid;
    for (int kt = 0; kt < 16; kt++) {
        if (kt < 15) { stage((kt + 1) & 1, (kt + 1) * 32); cp_commit(); cp_wait<1>(); }
        else cp_wait<0>();
        __syncthreads();
        const uint32_t* Af = reinterpret_cast<const uint32_t*>(&As[kt & 1][0]);
        const uint32_t* Bf = reinterpret_cast<const uint32_t*>(&Bs[kt & 1][0]);
        #pragma unroll
        for (int ks = 0; ks < 4; ks++) {
            uint32_t a0 = Af[rowa * 36 + ks * 8 + t4];
            uint32_t a1 = Af[(rowa + 8) * 36 + ks * 8 + t4];
            uint32_t a2 = Af[rowa * 36 + ks * 8 + t4 + 4];
            uint32_t a3 = Af[(rowa + 8) * 36 + ks * 8 + t4 + 4];
            #pragma unroll
            for (int j = 0; j < 8; j++) {
                int nrow = j * 8 + gid;
                mma_tf32(acc[j], a0, a1, a2, a3,
                         Bf[nrow * 36 + ks * 8 + t4], Bf[nrow * 36 + ks * 8 + t4 + 4]);
            }
        }
        __syncthreads();
    }
    #pragma unroll
    for (int j = 0; j < 8; j++) {
        int col = n0 + j * 8 + t4 * 2;
        float c0 = g_cvec[col], c1 = g_cvec[col + 1];
        *reinterpret_cast<float2*>(out + (size_t)(m0 + rowa) * 1024 + col) =
            make_float2(acc[j][0] + c0, acc[j][1] + c1);
        *reinterpret_cast<float2*>(out + (size_t)(m0 + rowa + 8) * 1024 + col) =
            make_float2(acc[j][2] + c0, acc[j][3] + c1);
    }
}

extern "C" void kernel_launch(void* const* d_in, const int* in_sizes, int n_in,
                              void* d_out, int out_size) {
    (void)in_sizes; (void)n_in; (void)out_size;
    const float*   queries = (const float*)d_in[0];
    const float*   keys    = (const float*)d_in[1];
    const float*   values  = (const float*)d_in[2];
    const uint8_t* mask    = (const uint8_t*)d_in[3];
    const float*   weights = (const float*)d_in[4];
    const float*   Wk      = (const float*)d_in[5];
    const float*   bk      = (const float*)d_in[6];
    const float*   kfb     = (const float*)d_in[7];
    const float*   Wv      = (const float*)d_in[8];
    const float*   bv      = (const float*)d_in[9];
    const float*   vfb     = (const float*)d_in[10];
    // d_in[11] = k_sum: provably irrelevant (heads 8..15 output = v_sum)
    const float*   vsum    = (const float*)d_in[12];
    const float*   Wo      = (const float*)d_in[13];
    const float*   bo      = (const float*)d_in[14];
    float*         out     = (float*)d_out;

    cudaFuncSetAttribute(attn_kernel, cudaFuncAttributeMaxDynamicSharedMemorySize, ATTN_SMEM);

    detect_kernel<<<1, 256>>>((const uint32_t*)mask);                 // idx 0
    front_kernel<<<13952, 256>>>(keys, values, Wk, Wv, Wo, vsum, bo,
                                 mask);                               // idx 1 (repack+conv+cvec)
    gate_kernel<<<dim3(32, 8, 2), 256>>>(bk, kfb, bv, vfb);           // idx 2
    attn_kernel<<<dim3(16, 8, 2), 256, ATTN_SMEM>>>(queries, weights);// idx 3 (profiled)
    proj_kernel<<<dim3(32, 16), 256>>>(out);                          // idx 4
}